// round 2
// baseline (speedup 1.0000x reference)
#include <cuda_runtime.h>
#include <cstdint>

// Problem constants: prediction [M=16, K=16, N=16, B=2048, C=10] fp32.
// label [B]: declared int64 in the reference, but JAX x64 is disabled by
// default, so the device buffer is int32. Read as const int*.
// Output: scalar fp32 = mean over all (m,k,n,b) of (argmax_c pred == label[b]).
#define NC 10
#define NB 2048
#define N_SLICES (16 * 16 * 16 * 2048)      // 8,388,608 slices = 2^23
#define TPB 256
#define F2_PER_SLICE 5                       // 10 floats = 5 float2 (40 B)

__device__ unsigned int g_correct_count;

__global__ void zero_count_kernel() {
    g_correct_count = 0u;
}

__global__ __launch_bounds__(TPB) void accuracy_count_kernel(
    const float* __restrict__ pred,
    const int* __restrict__ label)
{
    __shared__ float2 tile[TPB * F2_PER_SLICE];   // 256 slices * 40 B = 10 KB
    __shared__ unsigned int warp_sums[TPB / 32];

    const int tid = threadIdx.x;
    const long long block_slice0 = (long long)blockIdx.x * TPB;

    // Coalesced staging: this block's 256 slices = 1280 contiguous float2.
    const float2* __restrict__ src =
        reinterpret_cast<const float2*>(pred) + block_slice0 * F2_PER_SLICE;
#pragma unroll
    for (int j = 0; j < F2_PER_SLICE; j++) {
        tile[j * TPB + tid] = src[(long long)j * TPB + tid];
    }
    __syncthreads();

    // Unpack this thread's slice (10 class scores) from shared.
    float v[NC];
#pragma unroll
    for (int j = 0; j < F2_PER_SLICE; j++) {
        float2 p = tile[tid * F2_PER_SLICE + j];
        v[2 * j]     = p.x;
        v[2 * j + 1] = p.y;
    }

    // First-max argmax over 10 classes (matches jnp.argmax tie-breaking).
    float best = v[0];
    int best_idx = 0;
#pragma unroll
    for (int c = 1; c < NC; c++) {
        if (v[c] > best) { best = v[c]; best_idx = c; }
    }

    const int slice = (int)(block_slice0 + tid);
    const int b = slice & (NB - 1);
    const int lab = label[b];                 // int32 device buffer
    const int correct = (best_idx == lab) ? 1 : 0;

    // Warp ballot -> popc -> block reduce -> one atomic per block (exact).
    unsigned int bal = __ballot_sync(0xFFFFFFFFu, correct);
    const int lane = tid & 31;
    const int wid  = tid >> 5;
    if (lane == 0) warp_sums[wid] = __popc(bal);
    __syncthreads();
    if (tid == 0) {
        unsigned int s = 0;
#pragma unroll
        for (int w = 0; w < TPB / 32; w++) s += warp_sums[w];
        atomicAdd(&g_correct_count, s);
    }
}

__global__ void finalize_kernel(float* __restrict__ out) {
    // N_SLICES = 2^23, so this division is exact in fp32.
    out[0] = (float)g_correct_count * (1.0f / (float)N_SLICES);
}

extern "C" void kernel_launch(void* const* d_in, const int* in_sizes, int n_in,
                              void* d_out, int out_size) {
    const float* pred = (const float*)d_in[0];
    const int* label = (const int*)d_in[1];
    float* out = (float*)d_out;

    zero_count_kernel<<<1, 1>>>();
    accuracy_count_kernel<<<N_SLICES / TPB, TPB>>>(pred, label);
    finalize_kernel<<<1, 1>>>(out);
}